// round 11
// baseline (speedup 1.0000x reference)
#include <cuda_runtime.h>
#include <cuda_fp16.h>
#include <math.h>
#include <stdint.h>

#define N_LEVELS   16
#define N_DQ       9            // levels 0..8: dense fp16 quad grid
#define HASH_BITS  19
#define TABLE_SIZE (1u << HASH_BITS)
#define HASH_MASK  (TABLE_SIZE - 1u)
#define PRIME2     2654435761u
#define PRIME3     805459861u
#define FSCALE     256.0f
#define INV_FSCALE (1.0f / 256.0f)

// Dense fp16 quad grid, levels 0..8: entry(cx,cy,cz) = 16B =
//   {h2(y0z0), h2(y0z1), h2(y1z0), h2(y1z1)}, h2 = half2(256*f0, 256*f1)
#define DQ_CAP 2200000
__device__ uint4 g_dq[DQ_CAP];                       // ~35 MB

// Two-delta fp16 z-paired hash tables, 5 levels (9,10,11,13,14) x 2 deltas
#define N_ZP 5
__device__ uint2 g_zp2[(size_t)(2 * N_ZP) << HASH_BITS];   // ~42 MB

// Pow2-res fp16 quad hash tables, 2 levels (12,15)
#define N_Q2 2
__device__ uint4 g_q2[(size_t)N_Q2 << HASH_BITS];          // ~17 MB

struct Params {
    int      res[N_LEVELS];
    int      kind[N_LEVELS];     // 0 dense quad, 1 two-delta zpair, 2 pow2 quad
    int      base[N_LEVELS];
    unsigned dA[N_LEVELS];       // zp: P3*d       q2: Dz = P3*step
    unsigned dB[N_LEVELS];       // zp: P3*(d+1)   q2: Dy = P2*step
    int      dq_prefix[N_DQ + 1];
    int      zp_levels[N_ZP];
    int      q2_levels[N_Q2];
    int      blocks_dq, blocks_zp;
    int      total_dq, total_zp, total_q2;
};

// XLA-GPU lowers f32 divide to div.full.f32 (approx). The hash trunc
// amplifies 1-ulp differences into wrong indices; reproduce the instruction.
__device__ __forceinline__ float div_full(float a, float b) {
    float r;
    asm("div.full.f32 %0, %1, %2;" : "=f"(r) : "f"(a), "f"(b));
    return r;
}

__device__ __forceinline__ unsigned hash_part(int c, float fres, unsigned prime) {
    float cfrac = div_full((float)c, fres);
    // (cfrac+1)*0.5*2^18 == (cfrac+1)*2^17 exactly (power-of-2 scalings exact)
    float qf = __fmul_rn(__fadd_rn(cfrac, 1.0f), 131072.0f);
    unsigned q = (unsigned)qf;            // positive -> trunc == astype(int64)
    return q * prime;                      // uint32 wrap OK: 2^19 | 2^32
}

__device__ __forceinline__ unsigned pack_h2(float2 v) {
    __half2 h = __floats2half2_rn(v.x * FSCALE, v.y * FSCALE);
    return *reinterpret_cast<unsigned*>(&h);
}
__device__ __forceinline__ float2 unpack_h2(unsigned u) {
    __half2 h = *reinterpret_cast<__half2*>(&u);
    return __half22float2(h);
}

__device__ __forceinline__ void stcs_f2(float2* p, float2 v) {
    asm volatile("st.global.cs.v2.f32 [%0], {%1, %2};"
                 :: "l"(p), "f"(v.x), "f"(v.y) : "memory");
}

// ---------------------------------------------------------------------------
// Fused fill kernel (block-granular regions; dq shfl stays warp-uniform).
// ---------------------------------------------------------------------------
__global__ void __launch_bounds__(256)
fill_all_kernel(const float* __restrict__ tables, Params p)
{
    int b = blockIdx.x;

    if (b < p.blocks_dq) {
        int tid0 = b * 256 + threadIdx.x;
        bool valid = tid0 < p.total_dq;
        int tid = valid ? tid0 : (p.total_dq - 1);

        int level = 0;
#pragma unroll
        for (int i = 0; i < N_DQ; i++)
            if (tid >= p.dq_prefix[i + 1]) level = i + 1;

        int r   = tid - p.dq_prefix[level];
        int res = p.res[level];
        int cz = r % res;
        int t  = r / res;
        int cy = t % res;
        int cx = t / res;
        int cy1 = (cy + 1 == res) ? 0 : cy + 1;

        float fres = (float)res;
        unsigned hx  = hash_part(cx,  fres, 1u);
        unsigned hy  = hash_part(cy,  fres, PRIME2);
        unsigned hy1 = hash_part(cy1, fres, PRIME2);
        unsigned hz  = hash_part(cz,  fres, PRIME3);

        const float2* tab = reinterpret_cast<const float2*>(tables)
                            + (size_t)level * TABLE_SIZE;
        float2 v00 = __ldg(tab + ((hx + hy  + hz) & HASH_MASK));
        float2 v10 = __ldg(tab + ((hx + hy1 + hz) & HASH_MASK));

        int lane = threadIdx.x & 31;
        float a0 = __shfl_down_sync(0xFFFFFFFFu, v00.x, 1);
        float a1 = __shfl_down_sync(0xFFFFFFFFu, v00.y, 1);
        float b0 = __shfl_down_sync(0xFFFFFFFFu, v10.x, 1);
        float b1 = __shfl_down_sync(0xFFFFFFFFu, v10.y, 1);
        float2 v01, v11;
        if (valid && cz < res - 1 && lane < 31 && tid0 + 1 < p.total_dq) {
            v01 = make_float2(a0, a1);
            v11 = make_float2(b0, b1);
        } else {
            int z1 = (cz + 1 == res) ? 0 : cz + 1;
            unsigned hz1 = hash_part(z1, fres, PRIME3);
            v01 = __ldg(tab + ((hx + hy  + hz1) & HASH_MASK));
            v11 = __ldg(tab + ((hx + hy1 + hz1) & HASH_MASK));
        }

        if (valid) {
            uint4 e;
            e.x = pack_h2(v00);
            e.y = pack_h2(v01);
            e.z = pack_h2(v10);
            e.w = pack_h2(v11);
            g_dq[(size_t)p.base[level] + ((cx * res + cy) * res + cz)] = e;
        }
    } else if (b < p.blocks_dq + p.blocks_zp) {
        int tid = (b - p.blocks_dq) * 256 + threadIdx.x;
        if (tid >= p.total_zp) return;
        int slot   = tid >> HASH_BITS;
        unsigned s = tid & HASH_MASK;
        int li  = slot >> 1;
        int lvl = p.zp_levels[li];
        unsigned D = (slot & 1) ? p.dB[lvl] : p.dA[lvl];

        const float2* tab = reinterpret_cast<const float2*>(tables)
                            + (size_t)lvl * TABLE_SIZE;
        float2 a = __ldg(tab + s);
        float2 c = __ldg(tab + ((s + D) & HASH_MASK));
        uint2 e;
        e.x = pack_h2(a);
        e.y = pack_h2(c);
        g_zp2[((size_t)slot << HASH_BITS) + s] = e;
    } else {
        int tid = (b - p.blocks_dq - p.blocks_zp) * 256 + threadIdx.x;
        if (tid >= p.total_q2) return;
        int slot   = tid >> HASH_BITS;
        unsigned s = tid & HASH_MASK;
        int lvl = p.q2_levels[slot];
        unsigned Dz = p.dA[lvl];
        unsigned Dy = p.dB[lvl];

        const float2* tab = reinterpret_cast<const float2*>(tables)
                            + (size_t)lvl * TABLE_SIZE;
        uint4 e;
        e.x = pack_h2(__ldg(tab + s));
        e.y = pack_h2(__ldg(tab + ((s + Dz) & HASH_MASK)));
        e.z = pack_h2(__ldg(tab + ((s + Dy) & HASH_MASK)));
        e.w = pack_h2(__ldg(tab + ((s + Dy + Dz) & HASH_MASK)));
        g_q2[((size_t)slot << HASH_BITS) + s] = e;
    }
}

// ---------------------------------------------------------------------------
// Main kernel: block = 64 points x 16 levels, 512 threads, 2 POINTS/THREAD.
// warp w = level w (branch-uniform); lane handles points l and l+32.
// Doubles per-thread MLP to hide L2 latency. Output via smem transpose.
// ---------------------------------------------------------------------------
__global__ void __launch_bounds__(512, 2)
hash_encoding_kernel(const float* __restrict__ x,
                     const float* __restrict__ tables,
                     float* __restrict__ out,
                     Params p,
                     int n_points)
{
    __shared__ float  xs[192];                // 64 points x 3 coords
    __shared__ float2 outs[64][N_LEVELS + 1]; // +1 pad vs bank conflicts

    int tid = threadIdx.x;
    int n0  = blockIdx.x * 64;

    if (tid < 192) {
        int gi = n0 * 3 + tid;
        xs[tid] = (gi < n_points * 3) ? __ldcs(&x[gi]) : 0.0f;
    }
    __syncthreads();

    int level = tid >> 5;        // warp index == level (uniform per warp)
    int l     = tid & 31;

    const int   res  = p.res[level];
    const float fres = (float)res;
    const int   kind = p.kind[level];

    int   c0[2][3], c1[2][3];
    float w[2][3][2];
#pragma unroll
    for (int k = 0; k < 2; k++) {
        int lp = l + 32 * k;
#pragma unroll
        for (int d = 0; d < 3; d++) {
            float xv = fminf(fmaxf(xs[lp * 3 + d], -1.0f), 1.0f);
            float coord = xv * fres;
            float cf    = floorf(coord);
            float lc    = coord - cf;
            int   ci    = (int)cf;
            w[k][d][0] = 1.0f - lc;
            w[k][d][1] = lc;
            int a = ci;
            if (a < 0)    a += res;
            if (a >= res) a -= res;
            c0[k][d] = a;
            int bb = a + 1; if (bb == res) bb = 0;
            c1[k][d] = bb;
        }
    }

    float acc0[2], acc1[2];

    if (kind == 0) {
        // ---- dense fp16 quad: 2 LDG.128 per point, 4 in flight ----
        const uint4* dq = g_dq + p.base[level];
        int rr = res;
        uint4 e0[2], e1[2];
#pragma unroll
        for (int k = 0; k < 2; k++) {
            e0[k] = __ldg(dq + ((c0[k][0] * rr + c0[k][1]) * rr + c0[k][2]));
            e1[k] = __ldg(dq + ((c1[k][0] * rr + c0[k][1]) * rr + c0[k][2]));
        }
#pragma unroll
        for (int k = 0; k < 2; k++) {
            float wx0 = w[k][0][0], wx1 = w[k][0][1];
            float wy0 = w[k][1][0], wy1 = w[k][1][1];
            float wz0 = w[k][2][0], wz1 = w[k][2][1];
            float2 a00 = unpack_h2(e0[k].x), a01 = unpack_h2(e0[k].y);
            float2 a10 = unpack_h2(e0[k].z), a11 = unpack_h2(e0[k].w);
            float2 b00 = unpack_h2(e1[k].x), b01 = unpack_h2(e1[k].y);
            float2 b10 = unpack_h2(e1[k].z), b11 = unpack_h2(e1[k].w);
            acc0[k] = (wx0 * (wy0 * (wz0 * a00.x + wz1 * a01.x) +
                              wy1 * (wz0 * a10.x + wz1 * a11.x)) +
                       wx1 * (wy0 * (wz0 * b00.x + wz1 * b01.x) +
                              wy1 * (wz0 * b10.x + wz1 * b11.x))) * INV_FSCALE;
            acc1[k] = (wx0 * (wy0 * (wz0 * a00.y + wz1 * a01.y) +
                              wy1 * (wz0 * a10.y + wz1 * a11.y)) +
                       wx1 * (wy0 * (wz0 * b00.y + wz1 * b01.y) +
                              wy1 * (wz0 * b10.y + wz1 * b11.y))) * INV_FSCALE;
        }
    } else {
        unsigned hx0[2], hx1[2], hy0[2], hy1[2], hz0[2], hz1[2];
#pragma unroll
        for (int k = 0; k < 2; k++) {
            hx0[k] = hash_part(c0[k][0], fres, 1u);
            hx1[k] = hash_part(c1[k][0], fres, 1u);
            hy0[k] = hash_part(c0[k][1], fres, PRIME2);
            hy1[k] = hash_part(c1[k][1], fres, PRIME2);
            hz0[k] = hash_part(c0[k][2], fres, PRIME3);
            hz1[k] = hash_part(c1[k][2], fres, PRIME3);
        }
        const float2* tab = reinterpret_cast<const float2*>(tables)
                            + (size_t)level * TABLE_SIZE;

        if (kind == 1) {
            // ---- two-delta zpair: 4 LDG.64 per point (8 in flight) ----
            int t[2];
            uint2 e[2][4];
#pragma unroll
            for (int k = 0; k < 2; k++) {
                unsigned diffz = hz1[k] - hz0[k];
                t[k] = -1;
                if (diffz == p.dA[level])      t[k] = 0;
                else if (diffz == p.dB[level]) t[k] = 1;
                if (t[k] >= 0) {
                    const uint2* zt = g_zp2 + ((size_t)p.base[level]
                                       + ((size_t)t[k] << HASH_BITS));
                    e[k][0] = __ldg(zt + ((hx0[k] + hy0[k] + hz0[k]) & HASH_MASK));
                    e[k][1] = __ldg(zt + ((hx0[k] + hy1[k] + hz0[k]) & HASH_MASK));
                    e[k][2] = __ldg(zt + ((hx1[k] + hy0[k] + hz0[k]) & HASH_MASK));
                    e[k][3] = __ldg(zt + ((hx1[k] + hy1[k] + hz0[k]) & HASH_MASK));
                }
            }
#pragma unroll
            for (int k = 0; k < 2; k++) {
                float wx0 = w[k][0][0], wx1 = w[k][0][1];
                float wy0 = w[k][1][0], wy1 = w[k][1][1];
                float wz0 = w[k][2][0], wz1 = w[k][2][1];
                if (t[k] >= 0) {
                    float2 p00a = unpack_h2(e[k][0].x), p00b = unpack_h2(e[k][0].y);
                    float2 p01a = unpack_h2(e[k][1].x), p01b = unpack_h2(e[k][1].y);
                    float2 p10a = unpack_h2(e[k][2].x), p10b = unpack_h2(e[k][2].y);
                    float2 p11a = unpack_h2(e[k][3].x), p11b = unpack_h2(e[k][3].y);
                    acc0[k] = (wx0 * (wy0 * (wz0 * p00a.x + wz1 * p00b.x) +
                                      wy1 * (wz0 * p01a.x + wz1 * p01b.x)) +
                               wx1 * (wy0 * (wz0 * p10a.x + wz1 * p10b.x) +
                                      wy1 * (wz0 * p11a.x + wz1 * p11b.x))) * INV_FSCALE;
                    acc1[k] = (wx0 * (wy0 * (wz0 * p00a.y + wz1 * p00b.y) +
                                      wy1 * (wz0 * p01a.y + wz1 * p01b.y)) +
                               wx1 * (wy0 * (wz0 * p10a.y + wz1 * p10b.y) +
                                      wy1 * (wz0 * p11a.y + wz1 * p11b.y))) * INV_FSCALE;
                } else {
                    float2 f000 = __ldg(tab + ((hx0[k] + hy0[k] + hz0[k]) & HASH_MASK));
                    float2 f001 = __ldg(tab + ((hx0[k] + hy0[k] + hz1[k]) & HASH_MASK));
                    float2 f010 = __ldg(tab + ((hx0[k] + hy1[k] + hz0[k]) & HASH_MASK));
                    float2 f011 = __ldg(tab + ((hx0[k] + hy1[k] + hz1[k]) & HASH_MASK));
                    float2 f100 = __ldg(tab + ((hx1[k] + hy0[k] + hz0[k]) & HASH_MASK));
                    float2 f101 = __ldg(tab + ((hx1[k] + hy0[k] + hz1[k]) & HASH_MASK));
                    float2 f110 = __ldg(tab + ((hx1[k] + hy1[k] + hz0[k]) & HASH_MASK));
                    float2 f111 = __ldg(tab + ((hx1[k] + hy1[k] + hz1[k]) & HASH_MASK));
                    acc0[k] = wx0 * (wy0 * (wz0 * f000.x + wz1 * f001.x) +
                                     wy1 * (wz0 * f010.x + wz1 * f011.x)) +
                              wx1 * (wy0 * (wz0 * f100.x + wz1 * f101.x) +
                                     wy1 * (wz0 * f110.x + wz1 * f111.x));
                    acc1[k] = wx0 * (wy0 * (wz0 * f000.y + wz1 * f001.y) +
                                     wy1 * (wz0 * f010.y + wz1 * f011.y)) +
                              wx1 * (wy0 * (wz0 * f100.y + wz1 * f101.y) +
                                     wy1 * (wz0 * f110.y + wz1 * f111.y));
                }
            }
        } else {
            // ---- pow2 quad: 2 LDG.128 per point (4 in flight) ----
            bool ok[2];
            uint4 e0[2], e1[2];
#pragma unroll
            for (int k = 0; k < 2; k++) {
                ok[k] = (hz1[k] - hz0[k] == p.dA[level]) &&
                        (hy1[k] - hy0[k] == p.dB[level]);
                if (ok[k]) {
                    const uint4* qt = g_q2 + (size_t)p.base[level];
                    e0[k] = __ldg(qt + ((hx0[k] + hy0[k] + hz0[k]) & HASH_MASK));
                    e1[k] = __ldg(qt + ((hx1[k] + hy0[k] + hz0[k]) & HASH_MASK));
                }
            }
#pragma unroll
            for (int k = 0; k < 2; k++) {
                float wx0 = w[k][0][0], wx1 = w[k][0][1];
                float wy0 = w[k][1][0], wy1 = w[k][1][1];
                float wz0 = w[k][2][0], wz1 = w[k][2][1];
                if (ok[k]) {
                    float2 a00 = unpack_h2(e0[k].x), a01 = unpack_h2(e0[k].y);
                    float2 a10 = unpack_h2(e0[k].z), a11 = unpack_h2(e0[k].w);
                    float2 b00 = unpack_h2(e1[k].x), b01 = unpack_h2(e1[k].y);
                    float2 b10 = unpack_h2(e1[k].z), b11 = unpack_h2(e1[k].w);
                    acc0[k] = (wx0 * (wy0 * (wz0 * a00.x + wz1 * a01.x) +
                                      wy1 * (wz0 * a10.x + wz1 * a11.x)) +
                               wx1 * (wy0 * (wz0 * b00.x + wz1 * b01.x) +
                                      wy1 * (wz0 * b10.x + wz1 * b11.x))) * INV_FSCALE;
                    acc1[k] = (wx0 * (wy0 * (wz0 * a00.y + wz1 * a01.y) +
                                      wy1 * (wz0 * a10.y + wz1 * a11.y)) +
                               wx1 * (wy0 * (wz0 * b00.y + wz1 * b01.y) +
                                      wy1 * (wz0 * b10.y + wz1 * b11.y))) * INV_FSCALE;
                } else {
                    float2 f000 = __ldg(tab + ((hx0[k] + hy0[k] + hz0[k]) & HASH_MASK));
                    float2 f001 = __ldg(tab + ((hx0[k] + hy0[k] + hz1[k]) & HASH_MASK));
                    float2 f010 = __ldg(tab + ((hx0[k] + hy1[k] + hz0[k]) & HASH_MASK));
                    float2 f011 = __ldg(tab + ((hx0[k] + hy1[k] + hz1[k]) & HASH_MASK));
                    float2 f100 = __ldg(tab + ((hx1[k] + hy0[k] + hz0[k]) & HASH_MASK));
                    float2 f101 = __ldg(tab + ((hx1[k] + hy0[k] + hz1[k]) & HASH_MASK));
                    float2 f110 = __ldg(tab + ((hx1[k] + hy1[k] + hz0[k]) & HASH_MASK));
                    float2 f111 = __ldg(tab + ((hx1[k] + hy1[k] + hz1[k]) & HASH_MASK));
                    acc0[k] = wx0 * (wy0 * (wz0 * f000.x + wz1 * f001.x) +
                                     wy1 * (wz0 * f010.x + wz1 * f011.x)) +
                              wx1 * (wy0 * (wz0 * f100.x + wz1 * f101.x) +
                                     wy1 * (wz0 * f110.x + wz1 * f111.x));
                    acc1[k] = wx0 * (wy0 * (wz0 * f000.y + wz1 * f001.y) +
                                     wy1 * (wz0 * f010.y + wz1 * f011.y)) +
                              wx1 * (wy0 * (wz0 * f100.y + wz1 * f101.y) +
                                     wy1 * (wz0 * f110.y + wz1 * f111.y));
                }
            }
        }
    }

#pragma unroll
    for (int k = 0; k < 2; k++)
        outs[l + 32 * k][level] = make_float2(acc0[k], acc1[k]);
    __syncthreads();

    // coalesced streaming output: 512 threads x 2 writes = 64 points x 16 lvls
#pragma unroll
    for (int k = 0; k < 2; k++) {
        int idx = tid + k * 512;
        int i = idx >> 4, j = idx & 15;
        int on = n0 + i;
        if (on < n_points) {
            stcs_f2(reinterpret_cast<float2*>(out) + (size_t)on * N_LEVELS + j,
                    outs[i][j]);
        }
    }
}

extern "C" void kernel_launch(void* const* d_in, const int* in_sizes, int n_in,
                              void* d_out, int out_size)
{
    const float* x      = (const float*)d_in[0];
    const float* tables = (const float*)d_in[1];
    float*       out    = (float*)d_out;

    int n_points = in_sizes[0] / 3;

    Params p;
    for (int i = 0; i < N_LEVELS; i++) {
        double r = 16.0 * pow(32.0, (double)i / 15.0);   // host libm pow
        p.res[i] = (int)r;
    }

    int off = 0;
    p.dq_prefix[0] = 0;
    for (int i = 0; i < N_DQ; i++) {
        p.kind[i] = 0;
        p.base[i] = off;
        p.dA[i] = 0; p.dB[i] = 0;
        int cnt = p.res[i] * p.res[i] * p.res[i];
        off += cnt;
        p.dq_prefix[i + 1] = p.dq_prefix[i] + cnt;
    }

    int n_zp = 0, n_q2 = 0;
    for (int lvl = N_DQ; lvl < N_LEVELS; lvl++) {
        int r = p.res[lvl];
        if ((r & (r - 1)) == 0) {
            unsigned step = 131072u / (unsigned)r;
            p.kind[lvl] = 2;
            p.base[lvl] = n_q2 << HASH_BITS;
            p.dA[lvl] = PRIME3 * step;
            p.dB[lvl] = PRIME2 * step;
            p.q2_levels[n_q2++] = lvl;
        } else {
            unsigned d = 131072u / (unsigned)r;
            p.kind[lvl] = 1;
            p.base[lvl] = (n_zp * 2) << HASH_BITS;
            p.dA[lvl] = PRIME3 * d;
            p.dB[lvl] = PRIME3 * (d + 1);
            p.zp_levels[n_zp++] = lvl;
        }
    }

    p.total_dq = p.dq_prefix[N_DQ];
    p.total_zp = (n_zp * 2) << HASH_BITS;
    p.total_q2 = n_q2 << HASH_BITS;
    p.blocks_dq = (p.total_dq + 255) / 256;
    p.blocks_zp = (p.total_zp + 255) / 256;
    int blocks_q2 = (p.total_q2 + 255) / 256;

    int fill_blocks = p.blocks_dq + p.blocks_zp + blocks_q2;
    fill_all_kernel<<<fill_blocks, 256>>>(tables, p);

    int blocks = (n_points + 63) / 64;
    hash_encoding_kernel<<<blocks, 512>>>(x, tables, out, p, n_points);
}

// round 12
// speedup vs baseline: 1.1688x; 1.1688x over previous
#include <cuda_runtime.h>
#include <cuda_fp16.h>
#include <math.h>
#include <stdint.h>

#define N_LEVELS   16
#define N_DQ       9            // levels 0..8: dense fp16 quad grid
#define HASH_BITS  19
#define TABLE_SIZE (1u << HASH_BITS)
#define HASH_MASK  (TABLE_SIZE - 1u)
#define PRIME2     2654435761u
#define PRIME3     805459861u
#define FSCALE     256.0f
#define INV_FSCALE (1.0f / 256.0f)

// Dense fp16 quad grid, levels 0..8: entry(cx,cy,cz) = 16B =
//   {h2(y0z0), h2(y0z1), h2(y1z0), h2(y1z1)}, h2 = half2(256*f0, 256*f1)
#define DQ_CAP 2200000
__device__ uint4 g_dq[DQ_CAP];                       // ~35 MB

// Three-delta fp16 z tables, 5 non-pow2 hashed levels (9,10,11,13,14):
//   T[s] = { h2(tab[s]), h2(tab[s+D0]), h2(tab[s+D1]), h2(tab[s+Dw]) }
//   D0 = P3*d, D1 = P3*(d+1), Dw = wrap delta hz(0)-hz(res-1). 16B entry.
#define N_ZP 5
__device__ uint4 g_zp4[(size_t)N_ZP << HASH_BITS];         // ~42 MB

// Pow2-res fp16 quad hash tables, 2 levels (12,15)
#define N_Q2 2
__device__ uint4 g_q2[(size_t)N_Q2 << HASH_BITS];          // ~17 MB

struct Params {
    int      res[N_LEVELS];
    int      kind[N_LEVELS];     // 0 dense quad, 1 three-delta z, 2 pow2 quad
    int      base[N_LEVELS];
    unsigned dA[N_LEVELS];       // zp: P3*d       q2: Dz = P3*step
    unsigned dB[N_LEVELS];       // zp: P3*(d+1)   q2: Dy = P2*step
    int      dq_prefix[N_DQ + 1];
    int      zp_levels[N_ZP];
    int      q2_levels[N_Q2];
    int      blocks_dq, blocks_zp;
    int      total_dq, total_zp, total_q2;
};

// XLA-GPU lowers f32 divide to div.full.f32 (approx). The hash trunc
// amplifies 1-ulp differences into wrong indices; reproduce the instruction.
__device__ __forceinline__ float div_full(float a, float b) {
    float r;
    asm("div.full.f32 %0, %1, %2;" : "=f"(r) : "f"(a), "f"(b));
    return r;
}

__device__ __forceinline__ unsigned hash_part(int c, float fres, unsigned prime) {
    float cfrac = div_full((float)c, fres);
    // (cfrac+1)*0.5*2^18 == (cfrac+1)*2^17 exactly (power-of-2 scalings exact)
    float qf = __fmul_rn(__fadd_rn(cfrac, 1.0f), 131072.0f);
    unsigned q = (unsigned)qf;            // positive -> trunc == astype(int64)
    return q * prime;                      // uint32 wrap OK: 2^19 | 2^32
}

__device__ __forceinline__ unsigned pack_h2(float2 v) {
    __half2 h = __floats2half2_rn(v.x * FSCALE, v.y * FSCALE);
    return *reinterpret_cast<unsigned*>(&h);
}
__device__ __forceinline__ float2 unpack_h2(unsigned u) {
    __half2 h = *reinterpret_cast<__half2*>(&u);
    return __half22float2(h);
}

__device__ __forceinline__ void stcs_f2(float2* p, float2 v) {
    asm volatile("st.global.cs.v2.f32 [%0], {%1, %2};"
                 :: "l"(p), "f"(v.x), "f"(v.y) : "memory");
}

// ---------------------------------------------------------------------------
// Fused fill kernel (block-granular regions; dq shfl stays warp-uniform).
// ---------------------------------------------------------------------------
__global__ void __launch_bounds__(256)
fill_all_kernel(const float* __restrict__ tables, Params p)
{
    int b = blockIdx.x;

    if (b < p.blocks_dq) {
        // ---- dense fp16 quad fill (levels 0..8) ----
        int tid0 = b * 256 + threadIdx.x;
        bool valid = tid0 < p.total_dq;
        int tid = valid ? tid0 : (p.total_dq - 1);

        int level = 0;
#pragma unroll
        for (int i = 0; i < N_DQ; i++)
            if (tid >= p.dq_prefix[i + 1]) level = i + 1;

        int r   = tid - p.dq_prefix[level];
        int res = p.res[level];
        int cz = r % res;
        int t  = r / res;
        int cy = t % res;
        int cx = t / res;
        int cy1 = (cy + 1 == res) ? 0 : cy + 1;

        float fres = (float)res;
        unsigned hx  = hash_part(cx,  fres, 1u);
        unsigned hy  = hash_part(cy,  fres, PRIME2);
        unsigned hy1 = hash_part(cy1, fres, PRIME2);
        unsigned hz  = hash_part(cz,  fres, PRIME3);

        const float2* tab = reinterpret_cast<const float2*>(tables)
                            + (size_t)level * TABLE_SIZE;
        float2 v00 = __ldg(tab + ((hx + hy  + hz) & HASH_MASK));
        float2 v10 = __ldg(tab + ((hx + hy1 + hz) & HASH_MASK));

        int lane = threadIdx.x & 31;
        float a0 = __shfl_down_sync(0xFFFFFFFFu, v00.x, 1);
        float a1 = __shfl_down_sync(0xFFFFFFFFu, v00.y, 1);
        float b0 = __shfl_down_sync(0xFFFFFFFFu, v10.x, 1);
        float b1 = __shfl_down_sync(0xFFFFFFFFu, v10.y, 1);
        float2 v01, v11;
        if (valid && cz < res - 1 && lane < 31 && tid0 + 1 < p.total_dq) {
            v01 = make_float2(a0, a1);
            v11 = make_float2(b0, b1);
        } else {
            int z1 = (cz + 1 == res) ? 0 : cz + 1;
            unsigned hz1 = hash_part(z1, fres, PRIME3);
            v01 = __ldg(tab + ((hx + hy  + hz1) & HASH_MASK));
            v11 = __ldg(tab + ((hx + hy1 + hz1) & HASH_MASK));
        }

        if (valid) {
            uint4 e;
            e.x = pack_h2(v00);
            e.y = pack_h2(v01);
            e.z = pack_h2(v10);
            e.w = pack_h2(v11);
            g_dq[(size_t)p.base[level] + ((cx * res + cy) * res + cz)] = e;
        }
    } else if (b < p.blocks_dq + p.blocks_zp) {
        // ---- three-delta z table fill (coalesced 4-stream reads) ----
        int tid = (b - p.blocks_dq) * 256 + threadIdx.x;
        if (tid >= p.total_zp) return;
        int slot   = tid >> HASH_BITS;
        unsigned s = tid & HASH_MASK;
        int lvl = p.zp_levels[slot];
        int res = p.res[lvl];
        float fres = (float)res;
        unsigned D0 = p.dA[lvl];
        unsigned D1 = p.dB[lvl];
        // wrap delta: hz(0) - hz(res-1), computed with the SAME device hash
        unsigned Dw = PRIME3 * 131072u - hash_part(res - 1, fres, PRIME3);

        const float2* tab = reinterpret_cast<const float2*>(tables)
                            + (size_t)lvl * TABLE_SIZE;
        uint4 e;
        e.x = pack_h2(__ldg(tab + s));
        e.y = pack_h2(__ldg(tab + ((s + D0) & HASH_MASK)));
        e.z = pack_h2(__ldg(tab + ((s + D1) & HASH_MASK)));
        e.w = pack_h2(__ldg(tab + ((s + Dw) & HASH_MASK)));
        g_zp4[((size_t)slot << HASH_BITS) + s] = e;
    } else {
        // ---- pow2 fp16 quad fill (levels 12,15) ----
        int tid = (b - p.blocks_dq - p.blocks_zp) * 256 + threadIdx.x;
        if (tid >= p.total_q2) return;
        int slot   = tid >> HASH_BITS;
        unsigned s = tid & HASH_MASK;
        int lvl = p.q2_levels[slot];
        unsigned Dz = p.dA[lvl];
        unsigned Dy = p.dB[lvl];

        const float2* tab = reinterpret_cast<const float2*>(tables)
                            + (size_t)lvl * TABLE_SIZE;
        uint4 e;
        e.x = pack_h2(__ldg(tab + s));
        e.y = pack_h2(__ldg(tab + ((s + Dz) & HASH_MASK)));
        e.z = pack_h2(__ldg(tab + ((s + Dy) & HASH_MASK)));
        e.w = pack_h2(__ldg(tab + ((s + Dy + Dz) & HASH_MASK)));
        g_q2[((size_t)slot << HASH_BITS) + s] = e;
    }
}

// ---------------------------------------------------------------------------
// Main kernel: block = 32 points x 16 levels (512 threads).
// warp w = level w (BRANCH-UNIFORM), lane = point. Output via smem transpose.
// kind-1 levels have NO common fallback: the 16B entry's .w word handles
// z-wrap via the constant wrap delta (f32 fallback only for step anomalies).
// ---------------------------------------------------------------------------
__global__ void __launch_bounds__(512)
hash_encoding_kernel(const float* __restrict__ x,
                     const float* __restrict__ tables,
                     float* __restrict__ out,
                     Params p,
                     int n_points)
{
    __shared__ float  xs[96];                 // 32 points x 3 coords
    __shared__ float2 outs[32][N_LEVELS + 1]; // +1 pad vs bank conflicts

    int tid = threadIdx.x;
    int n0  = blockIdx.x * 32;

    if (tid < 96) {
        int gi = n0 * 3 + tid;
        xs[tid] = (gi < n_points * 3) ? __ldcs(&x[gi]) : 0.0f;
    }
    __syncthreads();

    int level = tid >> 5;        // warp index == level (uniform per warp)
    int l     = tid & 31;        // point within block

    float xv[3];
#pragma unroll
    for (int d = 0; d < 3; d++)
        xv[d] = fminf(fmaxf(xs[l * 3 + d], -1.0f), 1.0f);

    const int   res  = p.res[level];
    const float fres = (float)res;

    int   c0[3], c1[3];
    float w[3][2];
#pragma unroll
    for (int d = 0; d < 3; d++) {
        float coord = xv[d] * fres;
        float cf    = floorf(coord);
        float lc    = coord - cf;
        int   ci    = (int)cf;
        w[d][0] = 1.0f - lc;
        w[d][1] = lc;
        // ci in [-res, res] -> floor-mod via predicated adds (no int div)
        int a = ci;
        if (a < 0)    a += res;
        if (a >= res) a -= res;
        c0[d] = a;
        int bb = a + 1; if (bb == res) bb = 0;
        c1[d] = bb;
    }

    float wx0 = w[0][0], wx1 = w[0][1];
    float wy0 = w[1][0], wy1 = w[1][1];
    float wz0 = w[2][0], wz1 = w[2][1];

    float acc0 = 0.0f, acc1 = 0.0f;
    int kind = p.kind[level];

    if (kind == 0) {
        // ---- dense fp16 quad: 2 LDG.128 = 8 corners ----
        const uint4* dq = g_dq + p.base[level];
        int rr = res;
        uint4 e0 = __ldg(dq + ((c0[0] * rr + c0[1]) * rr + c0[2]));
        uint4 e1 = __ldg(dq + ((c1[0] * rr + c0[1]) * rr + c0[2]));
        float2 a00 = unpack_h2(e0.x), a01 = unpack_h2(e0.y);
        float2 a10 = unpack_h2(e0.z), a11 = unpack_h2(e0.w);
        float2 b00 = unpack_h2(e1.x), b01 = unpack_h2(e1.y);
        float2 b10 = unpack_h2(e1.z), b11 = unpack_h2(e1.w);
        acc0 = (wx0 * (wy0 * (wz0 * a00.x + wz1 * a01.x) +
                       wy1 * (wz0 * a10.x + wz1 * a11.x)) +
                wx1 * (wy0 * (wz0 * b00.x + wz1 * b01.x) +
                       wy1 * (wz0 * b10.x + wz1 * b11.x))) * INV_FSCALE;
        acc1 = (wx0 * (wy0 * (wz0 * a00.y + wz1 * a01.y) +
                       wy1 * (wz0 * a10.y + wz1 * a11.y)) +
                wx1 * (wy0 * (wz0 * b00.y + wz1 * b01.y) +
                       wy1 * (wz0 * b10.y + wz1 * b11.y))) * INV_FSCALE;
    } else {
        unsigned hx0 = hash_part(c0[0], fres, 1u);
        unsigned hx1 = hash_part(c1[0], fres, 1u);
        unsigned hy0 = hash_part(c0[1], fres, PRIME2);
        unsigned hy1 = hash_part(c1[1], fres, PRIME2);
        unsigned hz0 = hash_part(c0[2], fres, PRIME3);
        unsigned hz1 = hash_part(c1[2], fres, PRIME3);
        unsigned diffz = hz1 - hz0;

        bool done = false;
        if (kind == 1) {
            // ---- three-delta z table: 4 LDG.128, word-select, no branch ----
            bool isA = (diffz == p.dA[level]);
            bool isB = (diffz == p.dB[level]);
            bool isW = (c1[2] == 0);                 // z-wrap
            if (isA | isB | isW) {
                const uint4* zt = g_zp4 + ((size_t)p.base[level]);
                uint4 e00 = __ldg(zt + ((hx0 + hy0 + hz0) & HASH_MASK));
                uint4 e01 = __ldg(zt + ((hx0 + hy1 + hz0) & HASH_MASK));
                uint4 e10 = __ldg(zt + ((hx1 + hy0 + hz0) & HASH_MASK));
                uint4 e11 = __ldg(zt + ((hx1 + hy1 + hz0) & HASH_MASK));
                unsigned s00 = isA ? e00.y : (isB ? e00.z : e00.w);
                unsigned s01 = isA ? e01.y : (isB ? e01.z : e01.w);
                unsigned s10 = isA ? e10.y : (isB ? e10.z : e10.w);
                unsigned s11 = isA ? e11.y : (isB ? e11.z : e11.w);
                float2 p00a = unpack_h2(e00.x), p00b = unpack_h2(s00);
                float2 p01a = unpack_h2(e01.x), p01b = unpack_h2(s01);
                float2 p10a = unpack_h2(e10.x), p10b = unpack_h2(s10);
                float2 p11a = unpack_h2(e11.x), p11b = unpack_h2(s11);
                acc0 = (wx0 * (wy0 * (wz0 * p00a.x + wz1 * p00b.x) +
                               wy1 * (wz0 * p01a.x + wz1 * p01b.x)) +
                        wx1 * (wy0 * (wz0 * p10a.x + wz1 * p10b.x) +
                               wy1 * (wz0 * p11a.x + wz1 * p11b.x))) * INV_FSCALE;
                acc1 = (wx0 * (wy0 * (wz0 * p00a.y + wz1 * p00b.y) +
                               wy1 * (wz0 * p01a.y + wz1 * p01b.y)) +
                        wx1 * (wy0 * (wz0 * p10a.y + wz1 * p10b.y) +
                               wy1 * (wz0 * p11a.y + wz1 * p11b.y))) * INV_FSCALE;
                done = true;
            }
        } else {
            if (diffz == p.dA[level] && (hy1 - hy0) == p.dB[level]) {
                const uint4* qt = g_q2 + (size_t)p.base[level];
                uint4 e0 = __ldg(qt + ((hx0 + hy0 + hz0) & HASH_MASK));
                uint4 e1 = __ldg(qt + ((hx1 + hy0 + hz0) & HASH_MASK));
                float2 a00 = unpack_h2(e0.x), a01 = unpack_h2(e0.y);
                float2 a10 = unpack_h2(e0.z), a11 = unpack_h2(e0.w);
                float2 b00 = unpack_h2(e1.x), b01 = unpack_h2(e1.y);
                float2 b10 = unpack_h2(e1.z), b11 = unpack_h2(e1.w);
                acc0 = (wx0 * (wy0 * (wz0 * a00.x + wz1 * a01.x) +
                               wy1 * (wz0 * a10.x + wz1 * a11.x)) +
                        wx1 * (wy0 * (wz0 * b00.x + wz1 * b01.x) +
                               wy1 * (wz0 * b10.x + wz1 * b11.x))) * INV_FSCALE;
                acc1 = (wx0 * (wy0 * (wz0 * a00.y + wz1 * a01.y) +
                               wy1 * (wz0 * a10.y + wz1 * a11.y)) +
                        wx1 * (wy0 * (wz0 * b00.y + wz1 * b01.y) +
                               wy1 * (wz0 * b10.y + wz1 * b11.y))) * INV_FSCALE;
                done = true;
            }
        }

        if (!done) {
            // ---- exact f32 fallback (rare: q2 wraps, step anomalies) ----
            const float2* tab = reinterpret_cast<const float2*>(tables)
                                + (size_t)level * TABLE_SIZE;
            float2 f000 = __ldg(tab + ((hx0 + hy0 + hz0) & HASH_MASK));
            float2 f001 = __ldg(tab + ((hx0 + hy0 + hz1) & HASH_MASK));
            float2 f010 = __ldg(tab + ((hx0 + hy1 + hz0) & HASH_MASK));
            float2 f011 = __ldg(tab + ((hx0 + hy1 + hz1) & HASH_MASK));
            float2 f100 = __ldg(tab + ((hx1 + hy0 + hz0) & HASH_MASK));
            float2 f101 = __ldg(tab + ((hx1 + hy0 + hz1) & HASH_MASK));
            float2 f110 = __ldg(tab + ((hx1 + hy1 + hz0) & HASH_MASK));
            float2 f111 = __ldg(tab + ((hx1 + hy1 + hz1) & HASH_MASK));
            acc0 = wx0 * (wy0 * (wz0 * f000.x + wz1 * f001.x) +
                          wy1 * (wz0 * f010.x + wz1 * f011.x)) +
                   wx1 * (wy0 * (wz0 * f100.x + wz1 * f101.x) +
                          wy1 * (wz0 * f110.x + wz1 * f111.x));
            acc1 = wx0 * (wy0 * (wz0 * f000.y + wz1 * f001.y) +
                          wy1 * (wz0 * f010.y + wz1 * f011.y)) +
                   wx1 * (wy0 * (wz0 * f100.y + wz1 * f101.y) +
                          wy1 * (wz0 * f110.y + wz1 * f111.y));
        }
    }

    outs[l][level] = make_float2(acc0, acc1);
    __syncthreads();

    // coalesced streaming output: 512 threads write 32 points x 16 levels
    int i = tid >> 4, j = tid & 15;
    int on = n0 + i;
    if (on < n_points) {
        stcs_f2(reinterpret_cast<float2*>(out) + (size_t)on * N_LEVELS + j,
                outs[i][j]);
    }
}

extern "C" void kernel_launch(void* const* d_in, const int* in_sizes, int n_in,
                              void* d_out, int out_size)
{
    const float* x      = (const float*)d_in[0];
    const float* tables = (const float*)d_in[1];
    float*       out    = (float*)d_out;

    int n_points = in_sizes[0] / 3;

    Params p;
    for (int i = 0; i < N_LEVELS; i++) {
        double r = 16.0 * pow(32.0, (double)i / 15.0);   // host libm pow
        p.res[i] = (int)r;
    }

    int off = 0;
    p.dq_prefix[0] = 0;
    for (int i = 0; i < N_DQ; i++) {
        p.kind[i] = 0;
        p.base[i] = off;
        p.dA[i] = 0; p.dB[i] = 0;
        int cnt = p.res[i] * p.res[i] * p.res[i];
        off += cnt;
        p.dq_prefix[i + 1] = p.dq_prefix[i] + cnt;
    }

    int n_zp = 0, n_q2 = 0;
    for (int lvl = N_DQ; lvl < N_LEVELS; lvl++) {
        int r = p.res[lvl];
        if ((r & (r - 1)) == 0) {
            unsigned step = 131072u / (unsigned)r;
            p.kind[lvl] = 2;
            p.base[lvl] = n_q2 << HASH_BITS;
            p.dA[lvl] = PRIME3 * step;
            p.dB[lvl] = PRIME2 * step;
            p.q2_levels[n_q2++] = lvl;
        } else {
            unsigned d = 131072u / (unsigned)r;
            p.kind[lvl] = 1;
            p.base[lvl] = n_zp << HASH_BITS;
            p.dA[lvl] = PRIME3 * d;
            p.dB[lvl] = PRIME3 * (d + 1);
            p.zp_levels[n_zp++] = lvl;
        }
    }

    p.total_dq = p.dq_prefix[N_DQ];
    p.total_zp = n_zp << HASH_BITS;
    p.total_q2 = n_q2 << HASH_BITS;
    p.blocks_dq = (p.total_dq + 255) / 256;
    p.blocks_zp = (p.total_zp + 255) / 256;
    int blocks_q2 = (p.total_q2 + 255) / 256;

    int fill_blocks = p.blocks_dq + p.blocks_zp + blocks_q2;
    fill_all_kernel<<<fill_blocks, 256>>>(tables, p);

    int blocks = (n_points + 31) / 32;
    hash_encoding_kernel<<<blocks, 512>>>(x, tables, out, p, n_points);
}